// round 13
// baseline (speedup 1.0000x reference)
#include <cuda_runtime.h>

#define NN 50000
#define EE 800000
#define GG 64
#define HH 64
#define LL 3
#define CC 4
#define NH (NN*HH)
#define NB 592                 // 4 blocks/SM x 148 SMs, all co-resident
#define NT 256
#define NODE_CHUNK 85          // ceil(50000/592)
#define WSTRIDE 65             // transposed-W row stride (bank-conflict-free)

// ---------------------------------------------------------------------------
// Scratch
// ---------------------------------------------------------------------------
__device__ __align__(16) float g_x[NH];
__device__ __align__(16) float g_h[NH];
__device__ int   g_rowptr[NN+1];
__device__ int   g_cursor[NN];
__device__ int   g_deg[NN];
__device__ int   g_csrc[EE];
__device__ float g_stats[LL*CC*128];
__device__ float g_z[GG*HH*LL];
__device__ float g_h1[GG*HH];
__device__ float g_bnp[128];
__device__ int   g_ccnt[CC];
__device__ int   g_coff[CC+1];
__device__ int   g_ccur[CC];
__device__ int   g_clist[NN];
__device__ int   g_bsum[NB];
__device__ int   g_boff[NB];
__device__ int   g_is64;
__device__ unsigned int g_bar_arrive;
__device__ unsigned int g_bar_gen;

__device__ __forceinline__ int load_idx(const void* p, long long i, int is64) {
    if (is64) return (int)((const long long*)p)[i];
    return ((const int*)p)[i];
}

__device__ __forceinline__ void bar64(int id) {
    asm volatile("bar.sync %0, 64;" :: "r"(id) : "memory");
}

// Software grid barrier (all NB blocks co-resident by construction)
__device__ __forceinline__ void grid_barrier() {
    __syncthreads();
    if (threadIdx.x == 0) {
        __threadfence();
        volatile unsigned int* genp = &g_bar_gen;
        unsigned int gen = *genp;
        if (atomicAdd(&g_bar_arrive, 1u) == NB - 1) {
            g_bar_arrive = 0;
            __threadfence();
            *genp = gen + 1;
        } else {
            while (*genp == gen) { }
        }
    }
    __syncthreads();
}

// 64-wide inner product; h via broadcast float4 LDS, W column via
// conflict-free scalar LDS from the stride-65 transposed tile.
__device__ __forceinline__ float mm64t(const float* hp, const float* wt, float bias) {
    const float4* hp4 = (const float4*)hp;
    float o0 = 0.f, o1 = 0.f, o2 = 0.f, o3 = 0.f;
#pragma unroll
    for (int j = 0; j < 16; ++j) {
        float4 hv = hp4[j];
        o0 += hv.x * wt[4*j+0];
        o1 += hv.y * wt[4*j+1];
        o2 += hv.z * wt[4*j+2];
        o3 += hv.w * wt[4*j+3];
    }
    return bias + ((o0 + o1) + (o2 + o3));
}

// ---------------------------------------------------------------------------
// Single persistent kernel: everything
// ---------------------------------------------------------------------------
__global__ void __launch_bounds__(NT, 4) persistent_kernel(
        const float* __restrict__ x, const int* __restrict__ cl,
        const void* __restrict__ eidx, const void* __restrict__ batch,
        const float* __restrict__ W1, const float* __restrict__ b1,
        const float* __restrict__ g1, const float* __restrict__ be1,
        const float* __restrict__ W2, const float* __restrict__ b2,
        const float* __restrict__ Wp1, const float* __restrict__ bp1,
        const float* __restrict__ gp,  const float* __restrict__ bep,
        const float* __restrict__ Wp2, const float* __restrict__ bp2,
        float* __restrict__ out) {
    __shared__ __align__(16) float Wsh1[64 * WSTRIDE];   // transposed: Wt[f*65+i]
    __shared__ __align__(16) float Wsh2[64 * WSTRIDE];
    __shared__ __align__(16) float hsh[4][64];
    __shared__ __align__(16) int   esh[4][2][64];        // reused as int sh[512] in scans
    __shared__ float s1sh[64], s2sh[64];

    const int tid = threadIdx.x;
    const int b   = blockIdx.x;
    const int gtid = b * NT + tid;
    const int gstride = NB * NT;
    const int sub = tid >> 6;
    const int f   = tid & 63;
    const int bid = sub + 1;

    // ---- P0: init + dtype detect ----
    for (int i = gtid; i < NH / 4; i += gstride)
        ((float4*)g_x)[i] = ((const float4*)x)[i];
    for (int i = gtid; i < NN; i += gstride) g_deg[i] = 0;
    for (int i = gtid; i < LL*CC*128; i += gstride) g_stats[i] = 0.f;
    for (int i = gtid; i < GG*HH*LL; i += gstride) g_z[i] = 0.f;
    if (gtid < CC) g_ccnt[gtid] = 0;
    if (b == 0) {
        const int* e32 = (const int*)eidx;
        int bad = 0;
        for (int k = tid; k < 1024; k += NT) if (e32[2 * k + 1] != 0) bad = 1;
        int* sh = (int*)esh;
        sh[tid] = bad;
        __syncthreads();
        for (int s = 128; s > 0; s >>= 1) {
            if (tid < s) sh[tid] |= sh[tid + s];
            __syncthreads();
        }
        if (tid == 0) g_is64 = !sh[0];
    }
    grid_barrier();
    const int is64 = g_is64;

    // ---- P1: degree + cluster count ----
    for (int i = gtid; i < EE; i += gstride) {
        int d = load_idx(eidx, (long long)EE + i, is64);
        atomicAdd(&g_deg[d], 1);
    }
    for (int i = gtid; i < NN; i += gstride) atomicAdd(&g_ccnt[cl[i]], 1);
    grid_barrier();

    // ---- P2: cluster offsets (block0) + local inclusive degree scans ----
    if (b == 0 && tid == 0) {
        int acc = 0;
        for (int c = 0; c < CC; ++c) { g_coff[c] = acc; g_ccur[c] = acc; acc += g_ccnt[c]; }
        g_coff[CC] = acc;
    }
    {
        int* sh = (int*)esh;
        int idx = b * NODE_CHUNK + tid;
        int v = (tid < NODE_CHUNK && idx < NN) ? g_deg[idx] : 0;
        sh[tid] = v;
        __syncthreads();
        for (int s = 1; s < NT; s <<= 1) {
            int tv = (tid >= s) ? sh[tid - s] : 0;
            __syncthreads();
            sh[tid] += tv;
            __syncthreads();
        }
        if (tid < NODE_CHUNK && idx < NN) g_rowptr[idx] = sh[tid];
        if (tid == NT - 1) g_bsum[b] = sh[NT - 1];
    }
    grid_barrier();

    // ---- P3: scan block sums (block0); fill cluster lists (all) ----
    if (b == 0 && tid == 0) {
        int acc = 0;
        for (int i = 0; i < NB; ++i) { int t = g_bsum[i]; g_boff[i] = acc; acc += t; }
        g_rowptr[NN] = acc;
    }
    for (int i = gtid; i < NN; i += gstride) {
        int pos = atomicAdd(&g_ccur[cl[i]], 1);
        g_clist[pos] = i;
    }
    grid_barrier();

    // ---- P4: finalize rowptr/cursor ----
    {
        int idx = b * NODE_CHUNK + tid;
        if (tid < NODE_CHUNK && idx < NN) {
            int excl = g_boff[b] + g_rowptr[idx] - g_deg[idx];
            g_rowptr[idx] = excl;
            g_cursor[idx] = excl;
        }
    }
    grid_barrier();

    // ---- P5: CSR fill ----
    for (int i = gtid; i < EE; i += gstride) {
        int s = load_idx(eidx, i, is64);
        int d = load_idx(eidx, (long long)EE + i, is64);
        int pos = atomicAdd(&g_cursor[d], 1);
        g_csrc[pos] = s;
    }
    grid_barrier();

    // ---- main loop: 3 layers x 4 clusters ----
    for (int t = 0; t < LL; ++t) {
        for (int c = 0; c < CC; ++c) {
            const int tc = t * CC + c;
            // stage both weight matrices transposed: Wt[f*WSTRIDE + i] = W[i*64+f]
            for (int idx = tid; idx < 4096; idx += NT) {
                int wi = idx >> 6, wf = idx & 63;
                Wsh1[wf * WSTRIDE + wi] = W1[tc * 4096 + idx];
                Wsh2[wf * WSTRIDE + wi] = W2[tc * 4096 + idx];
            }
            if (tid < 64) { s1sh[tid] = 0.f; s2sh[tid] = 0.f; }
            __syncthreads();

            // === phase A: gather + mm1 + stats ===
            const float* wt1 = Wsh1 + f * WSTRIDE;
            float bias = b1[tc * 64 + f];

            const int lo  = g_coff[c];
            const int cnt = g_coff[c + 1] - lo;
            const int per = NB * 4;
            const int base = b * 4 + sub;

            float a1 = 0.f, a2 = 0.f;
            int buf = 0;
            int node = 0, e0 = 0, deg = 0;
            float xv = 0.f;
            if (base < cnt) {
                node = g_clist[lo + base];
                e0   = g_rowptr[node];
                deg  = g_rowptr[node + 1] - e0;
                xv   = g_x[node * 64 + f];
                if (deg <= 64 && f < deg) esh[sub][0][f] = g_csrc[e0 + f];
            }
            bar64(bid);

            for (int pos = base; pos < cnt; pos += per) {
                float acc0 = xv, acc1 = 0.f, acc2 = 0.f, acc3 = 0.f;
                float acc4 = 0.f, acc5 = 0.f, acc6 = 0.f, acc7 = 0.f;
                if (deg <= 64) {
                    const int* ep = esh[sub][buf];
                    int i = 0;
                    for (; i + 8 <= deg; i += 8) {
                        int s0 = ep[i+0], s1 = ep[i+1], s2 = ep[i+2], s3 = ep[i+3];
                        int s4 = ep[i+4], s5 = ep[i+5], s6 = ep[i+6], s7 = ep[i+7];
                        acc0 += g_x[s0 * 64 + f];
                        acc1 += g_x[s1 * 64 + f];
                        acc2 += g_x[s2 * 64 + f];
                        acc3 += g_x[s3 * 64 + f];
                        acc4 += g_x[s4 * 64 + f];
                        acc5 += g_x[s5 * 64 + f];
                        acc6 += g_x[s6 * 64 + f];
                        acc7 += g_x[s7 * 64 + f];
                    }
                    for (; i < deg; ++i) acc0 += g_x[ep[i] * 64 + f];
                } else {
                    // rare (deg>64): direct-global gather (broadcast csrc reads)
                    int e = e0;
                    const int e1 = e0 + deg;
                    for (; e + 8 <= e1; e += 8) {
                        int s0 = g_csrc[e+0], s1 = g_csrc[e+1], s2 = g_csrc[e+2], s3 = g_csrc[e+3];
                        int s4 = g_csrc[e+4], s5 = g_csrc[e+5], s6 = g_csrc[e+6], s7 = g_csrc[e+7];
                        acc0 += g_x[s0 * 64 + f];
                        acc1 += g_x[s1 * 64 + f];
                        acc2 += g_x[s2 * 64 + f];
                        acc3 += g_x[s3 * 64 + f];
                        acc4 += g_x[s4 * 64 + f];
                        acc5 += g_x[s5 * 64 + f];
                        acc6 += g_x[s6 * 64 + f];
                        acc7 += g_x[s7 * 64 + f];
                    }
                    for (; e < e1; ++e) acc0 += g_x[g_csrc[e] * 64 + f];
                }
                hsh[sub][f] = ((acc0 + acc1) + (acc2 + acc3)) + ((acc4 + acc5) + (acc6 + acc7));

                int npos = pos + per;
                int nnode = 0, ne0 = 0, ndeg = 0;
                float nxv = 0.f;
                if (npos < cnt) {
                    nnode = g_clist[lo + npos];
                    ne0   = g_rowptr[nnode];
                    ndeg  = g_rowptr[nnode + 1] - ne0;
                    nxv   = g_x[nnode * 64 + f];
                    if (ndeg <= 64 && f < ndeg) esh[sub][buf ^ 1][f] = g_csrc[ne0 + f];
                }
                bar64(bid);
                float o = mm64t(hsh[sub], wt1, bias);
                g_h[node * 64 + f] = o;
                a1 += o; a2 += o * o;
                bar64(bid);

                node = nnode; e0 = ne0; deg = ndeg; xv = nxv; buf ^= 1;
            }
            atomicAdd(&s1sh[f], a1);
            atomicAdd(&s2sh[f], a2);
            __syncthreads();
            if (tid < 64) {
                atomicAdd(&g_stats[tc * 128 + tid],      s1sh[tid]);
                atomicAdd(&g_stats[tc * 128 + 64 + tid], s2sh[tid]);
            }
            grid_barrier();

            // === phase B: BN + ReLU + mm2, write back x ===
            const float* wt2 = Wsh2 + f * WSTRIDE;
            float bias2 = b2[tc * 64 + f];
            float cnt_f = (float)max(cnt, 1);
            float mean  = g_stats[tc * 128 + f] / cnt_f;
            float var   = g_stats[tc * 128 + 64 + f] / cnt_f - mean * mean;
            float inv   = rsqrtf(var + 1e-5f) * g1[tc * 64 + f];
            float beta  = be1[tc * 64 + f];

            int node2 = 0;
            float hv = 0.f;
            if (base < cnt) {
                node2 = g_clist[lo + base];
                hv    = g_h[node2 * 64 + f];
            }
            for (int pos = base; pos < cnt; pos += per) {
                hsh[sub][f] = fmaxf((hv - mean) * inv + beta, 0.f);
                int npos = pos + per;
                int nnode = 0;
                float nhv = 0.f;
                if (npos < cnt) {
                    nnode = g_clist[lo + npos];
                    nhv   = g_h[nnode * 64 + f];
                }
                bar64(bid);
                g_x[node2 * 64 + f] = mm64t(hsh[sub], wt2, bias2);
                bar64(bid);
                node2 = nnode; hv = nhv;
            }
            grid_barrier();
        }

        // ---- pooling for layer t: 256 blocks = 64 graphs x 4 chunks ----
        if (b < GG * 4) {
            const int g  = b >> 2;
            const int ch = b & 3;
            int* lohi = (int*)esh;
            if (tid < 2) {
                int target = g + tid;
                int lo2 = 0, hi2 = NN;
                while (lo2 < hi2) {
                    int m = (lo2 + hi2) >> 1;
                    if (load_idx(batch, m, is64) < target) lo2 = m + 1; else hi2 = m;
                }
                lohi[tid] = lo2;
            }
            __syncthreads();
            int lo2 = lohi[0], hi2 = lohi[1];
            int len = hi2 - lo2;
            int clo = lo2 + ((len * ch) >> 2);
            int chi = lo2 + ((len * (ch + 1)) >> 2);
            float s0 = 0.f, s1 = 0.f;
            int r = clo + sub;
            for (; r + 8 <= chi; r += 8) {
                s0 += g_x[r * 64 + f];
                s1 += g_x[(r + 4) * 64 + f];
            }
            for (; r < chi; r += 4) s0 += g_x[r * 64 + f];
            hsh[sub][f] = s0 + s1;
            __syncthreads();
            if (sub == 0) {
                float v = hsh[0][f] + hsh[1][f] + hsh[2][f] + hsh[3][f];
                atomicAdd(&g_z[g * (HH * LL) + t * 64 + f], v);
            }
        }
        grid_barrier();
    }

    // ---- F1: h1[g] = z[g] @ Wp1 + bp1 ----
    if (b < GG) {
        float* zsh = Wsh1;
        if (tid < HH * LL) zsh[tid] = g_z[b * (HH * LL) + tid];
        __syncthreads();
        float p = 0.f;
        int k0 = sub * 48;
#pragma unroll
        for (int k = 0; k < 48; ++k) p += zsh[k0 + k] * Wp1[(k0 + k) * 64 + f];
        hsh[sub][f] = p;
        __syncthreads();
        if (sub == 0)
            g_h1[b * 64 + f] = bp1[f] + ((hsh[0][f] + hsh[1][f]) + (hsh[2][f] + hsh[3][f]));
    }
    grid_barrier();

    // ---- F2: BN stats over graph rows (block 0) ----
    if (b == 0 && tid < 64) {
        float s = 0.f, q = 0.f;
        for (int g = 0; g < GG; ++g) { float v = g_h1[g * 64 + tid]; s += v; q += v * v; }
        float mean = s / (float)GG;
        float var  = q / (float)GG - mean * mean;
        g_bnp[tid]      = mean;
        g_bnp[64 + tid] = rsqrtf(var + 1e-5f) * gp[tid];
    }
    grid_barrier();

    // ---- F3: out[g] = relu(bn(h1[g])) @ Wp2 + bp2 ----
    if (b < GG) {
        float* vsh = Wsh1;
        if (tid < 64) {
            float v = g_h1[b * 64 + tid];
            vsh[tid] = fmaxf((v - g_bnp[tid]) * g_bnp[64 + tid] + bep[tid], 0.f);
        }
        __syncthreads();
        float p = 0.f;
        int k0 = sub * 16;
#pragma unroll
        for (int k = 0; k < 16; ++k) p += vsh[k0 + k] * Wp2[(k0 + k) * 64 + f];
        hsh[sub][f] = p;
        __syncthreads();
        if (sub == 0)
            out[b * 64 + f] = bp2[f] + ((hsh[0][f] + hsh[1][f]) + (hsh[2][f] + hsh[3][f]));
    }
}

// ---------------------------------------------------------------------------
extern "C" void kernel_launch(void* const* d_in, const int* in_sizes, int n_in,
                              void* d_out, int out_size) {
    const float* x     = (const float*)d_in[0];
    const int*   cl    = (const int*)d_in[1];
    const void*  eidx  = d_in[2];
    const void*  batch = d_in[3];
    const float* W1  = (const float*)d_in[4];
    const float* b1  = (const float*)d_in[5];
    const float* g1  = (const float*)d_in[6];
    const float* be1 = (const float*)d_in[7];
    const float* W2  = (const float*)d_in[8];
    const float* b2  = (const float*)d_in[9];
    const float* Wp1 = (const float*)d_in[10];
    const float* bp1 = (const float*)d_in[11];
    const float* gp  = (const float*)d_in[12];
    const float* bep = (const float*)d_in[13];
    const float* Wp2 = (const float*)d_in[14];
    const float* bp2 = (const float*)d_in[15];
    float* out = (float*)d_out;

    persistent_kernel<<<NB, NT>>>(x, cl, eidx, batch, W1, b1, g1, be1, W2, b2,
                                  Wp1, bp1, gp, bep, Wp2, bp2, out);
}

// round 14
// speedup vs baseline: 1.4648x; 1.4648x over previous
#include <cuda_runtime.h>

#define NN 50000
#define EE 800000
#define GG 64
#define HH 64
#define LL 3
#define CC 4
#define NH (NN*HH)
#define NB 444                 // 3 blocks/SM x 148 SMs, all co-resident
#define NT 256
#define NODE_CHUNK 113         // ceil(50000/444)
#define WSTRIDE 65             // transposed-W row stride (bank-conflict-free)

// ---------------------------------------------------------------------------
// Scratch
// ---------------------------------------------------------------------------
__device__ __align__(16) float g_x[NH];
__device__ __align__(16) float g_h[NH];
__device__ int   g_rowptr[NN+1];
__device__ int   g_cursor[NN];
__device__ int   g_deg[NN];
__device__ int   g_csrc[EE];
__device__ float g_stats[LL*CC*128];
__device__ float g_z[GG*HH*LL];
__device__ float g_h1[GG*HH];
__device__ float g_bnp[128];
__device__ int   g_ccnt[CC];
__device__ int   g_coff[CC+1];
__device__ int   g_ccur[CC];
__device__ int   g_clist[NN];
__device__ int   g_bsum[NB];
__device__ int   g_boff[NB];
__device__ int   g_is64;
__device__ unsigned int g_bar_arrive;
__device__ unsigned int g_bar_gen;

__device__ __forceinline__ int load_idx(const void* p, long long i, int is64) {
    if (is64) return (int)((const long long*)p)[i];
    return ((const int*)p)[i];
}

__device__ __forceinline__ void bar64(int id) {
    asm volatile("bar.sync %0, 64;" :: "r"(id) : "memory");
}

// Software grid barrier (all NB blocks co-resident by construction)
__device__ __forceinline__ void grid_barrier() {
    __syncthreads();
    if (threadIdx.x == 0) {
        __threadfence();
        volatile unsigned int* genp = &g_bar_gen;
        unsigned int gen = *genp;
        if (atomicAdd(&g_bar_arrive, 1u) == NB - 1) {
            g_bar_arrive = 0;
            __threadfence();
            *genp = gen + 1;
        } else {
            while (*genp == gen) { }
        }
    }
    __syncthreads();
}

// 64-wide inner product; h via broadcast float4 LDS, W column via
// conflict-free scalar LDS from the stride-65 transposed tile.
__device__ __forceinline__ float mm64t(const float* hp, const float* wt, float bias) {
    const float4* hp4 = (const float4*)hp;
    float o0 = 0.f, o1 = 0.f, o2 = 0.f, o3 = 0.f;
#pragma unroll
    for (int j = 0; j < 16; ++j) {
        float4 hv = hp4[j];
        o0 += hv.x * wt[4*j+0];
        o1 += hv.y * wt[4*j+1];
        o2 += hv.z * wt[4*j+2];
        o3 += hv.w * wt[4*j+3];
    }
    return bias + ((o0 + o1) + (o2 + o3));
}

// ---------------------------------------------------------------------------
// Single persistent kernel: everything
// ---------------------------------------------------------------------------
__global__ void __launch_bounds__(NT, 3) persistent_kernel(
        const float* __restrict__ x, const int* __restrict__ cl,
        const void* __restrict__ eidx, const void* __restrict__ batch,
        const float* __restrict__ W1, const float* __restrict__ b1,
        const float* __restrict__ g1, const float* __restrict__ be1,
        const float* __restrict__ W2, const float* __restrict__ b2,
        const float* __restrict__ Wp1, const float* __restrict__ bp1,
        const float* __restrict__ gp,  const float* __restrict__ bep,
        const float* __restrict__ Wp2, const float* __restrict__ bp2,
        float* __restrict__ out) {
    __shared__ __align__(16) float Wsh1[64 * WSTRIDE];   // transposed: Wt[f*65+i]
    __shared__ __align__(16) float Wsh2[64 * WSTRIDE];
    __shared__ __align__(16) float hsh[4][64];
    __shared__ __align__(16) int   esh[4][2][64];        // reused as int sh[512] in scans
    __shared__ float s1sh[64], s2sh[64];

    const int tid = threadIdx.x;
    const int b   = blockIdx.x;
    const int gtid = b * NT + tid;
    const int gstride = NB * NT;
    const int sub = tid >> 6;
    const int f   = tid & 63;
    const int bid = sub + 1;

    // ---- P0: init + dtype detect ----
    for (int i = gtid; i < NH / 4; i += gstride)
        ((float4*)g_x)[i] = ((const float4*)x)[i];
    for (int i = gtid; i < NN; i += gstride) g_deg[i] = 0;
    for (int i = gtid; i < LL*CC*128; i += gstride) g_stats[i] = 0.f;
    for (int i = gtid; i < GG*HH*LL; i += gstride) g_z[i] = 0.f;
    if (gtid < CC) g_ccnt[gtid] = 0;
    if (b == 0) {
        const int* e32 = (const int*)eidx;
        int bad = 0;
        for (int k = tid; k < 1024; k += NT) if (e32[2 * k + 1] != 0) bad = 1;
        int* sh = (int*)esh;
        sh[tid] = bad;
        __syncthreads();
        for (int s = 128; s > 0; s >>= 1) {
            if (tid < s) sh[tid] |= sh[tid + s];
            __syncthreads();
        }
        if (tid == 0) g_is64 = !sh[0];
    }
    grid_barrier();
    const int is64 = g_is64;

    // ---- P1: degree + cluster count ----
    for (int i = gtid; i < EE; i += gstride) {
        int d = load_idx(eidx, (long long)EE + i, is64);
        atomicAdd(&g_deg[d], 1);
    }
    for (int i = gtid; i < NN; i += gstride) atomicAdd(&g_ccnt[cl[i]], 1);
    grid_barrier();

    // ---- P2: cluster offsets (block0) + local inclusive degree scans ----
    if (b == 0 && tid == 0) {
        int acc = 0;
        for (int c = 0; c < CC; ++c) { g_coff[c] = acc; g_ccur[c] = acc; acc += g_ccnt[c]; }
        g_coff[CC] = acc;
    }
    {
        int* sh = (int*)esh;
        int idx = b * NODE_CHUNK + tid;
        int v = (tid < NODE_CHUNK && idx < NN) ? g_deg[idx] : 0;
        sh[tid] = v;
        __syncthreads();
        for (int s = 1; s < NT; s <<= 1) {
            int tv = (tid >= s) ? sh[tid - s] : 0;
            __syncthreads();
            sh[tid] += tv;
            __syncthreads();
        }
        if (tid < NODE_CHUNK && idx < NN) g_rowptr[idx] = sh[tid];
        if (tid == NT - 1) g_bsum[b] = sh[NT - 1];
    }
    grid_barrier();

    // ---- P3: scan block sums (block0); fill cluster lists (all) ----
    if (b == 0 && tid == 0) {
        int acc = 0;
        for (int i = 0; i < NB; ++i) { int t = g_bsum[i]; g_boff[i] = acc; acc += t; }
        g_rowptr[NN] = acc;
    }
    for (int i = gtid; i < NN; i += gstride) {
        int pos = atomicAdd(&g_ccur[cl[i]], 1);
        g_clist[pos] = i;
    }
    grid_barrier();

    // ---- P4: finalize rowptr/cursor ----
    {
        int idx = b * NODE_CHUNK + tid;
        if (tid < NODE_CHUNK && idx < NN) {
            int excl = g_boff[b] + g_rowptr[idx] - g_deg[idx];
            g_rowptr[idx] = excl;
            g_cursor[idx] = excl;
        }
    }
    grid_barrier();

    // ---- P5: CSR fill ----
    for (int i = gtid; i < EE; i += gstride) {
        int s = load_idx(eidx, i, is64);
        int d = load_idx(eidx, (long long)EE + i, is64);
        int pos = atomicAdd(&g_cursor[d], 1);
        g_csrc[pos] = s;
    }
    grid_barrier();

    // ---- main loop: 3 layers x 4 clusters ----
    for (int t = 0; t < LL; ++t) {
        for (int c = 0; c < CC; ++c) {
            const int tc = t * CC + c;
            // stage both weight matrices transposed: Wt[f*WSTRIDE + i] = W[i*64+f]
            for (int idx = tid; idx < 4096; idx += NT) {
                int wi = idx >> 6, wf = idx & 63;
                Wsh1[wf * WSTRIDE + wi] = W1[tc * 4096 + idx];
                Wsh2[wf * WSTRIDE + wi] = W2[tc * 4096 + idx];
            }
            if (tid < 64) { s1sh[tid] = 0.f; s2sh[tid] = 0.f; }
            __syncthreads();

            // === phase A: gather + mm1 + stats ===
            const float* wt1 = Wsh1 + f * WSTRIDE;
            float bias = b1[tc * 64 + f];

            const int lo  = g_coff[c];
            const int cnt = g_coff[c + 1] - lo;
            const int per = NB * 4;
            const int base = b * 4 + sub;

            float a1 = 0.f, a2 = 0.f;
            int buf = 0;
            int node = 0, e0 = 0, deg = 0;
            float xv = 0.f;
            if (base < cnt) {
                node = g_clist[lo + base];
                e0   = g_rowptr[node];
                deg  = g_rowptr[node + 1] - e0;
                xv   = g_x[node * 64 + f];
                if (deg <= 64 && f < deg) esh[sub][0][f] = g_csrc[e0 + f];
            }
            bar64(bid);

            for (int pos = base; pos < cnt; pos += per) {
                float acc0 = xv, acc1 = 0.f, acc2 = 0.f, acc3 = 0.f;
                float acc4 = 0.f, acc5 = 0.f, acc6 = 0.f, acc7 = 0.f;
                if (deg <= 64) {
                    const int* ep = esh[sub][buf];
                    int i = 0;
                    for (; i + 8 <= deg; i += 8) {
                        int s0 = ep[i+0], s1 = ep[i+1], s2 = ep[i+2], s3 = ep[i+3];
                        int s4 = ep[i+4], s5 = ep[i+5], s6 = ep[i+6], s7 = ep[i+7];
                        acc0 += g_x[s0 * 64 + f];
                        acc1 += g_x[s1 * 64 + f];
                        acc2 += g_x[s2 * 64 + f];
                        acc3 += g_x[s3 * 64 + f];
                        acc4 += g_x[s4 * 64 + f];
                        acc5 += g_x[s5 * 64 + f];
                        acc6 += g_x[s6 * 64 + f];
                        acc7 += g_x[s7 * 64 + f];
                    }
                    for (; i < deg; ++i) acc0 += g_x[ep[i] * 64 + f];
                } else {
                    // rare (deg>64): direct-global gather (broadcast csrc reads)
                    int e = e0;
                    const int e1 = e0 + deg;
                    for (; e + 8 <= e1; e += 8) {
                        int s0 = g_csrc[e+0], s1 = g_csrc[e+1], s2 = g_csrc[e+2], s3 = g_csrc[e+3];
                        int s4 = g_csrc[e+4], s5 = g_csrc[e+5], s6 = g_csrc[e+6], s7 = g_csrc[e+7];
                        acc0 += g_x[s0 * 64 + f];
                        acc1 += g_x[s1 * 64 + f];
                        acc2 += g_x[s2 * 64 + f];
                        acc3 += g_x[s3 * 64 + f];
                        acc4 += g_x[s4 * 64 + f];
                        acc5 += g_x[s5 * 64 + f];
                        acc6 += g_x[s6 * 64 + f];
                        acc7 += g_x[s7 * 64 + f];
                    }
                    for (; e < e1; ++e) acc0 += g_x[g_csrc[e] * 64 + f];
                }
                hsh[sub][f] = ((acc0 + acc1) + (acc2 + acc3)) + ((acc4 + acc5) + (acc6 + acc7));

                int npos = pos + per;
                int nnode = 0, ne0 = 0, ndeg = 0;
                float nxv = 0.f;
                if (npos < cnt) {
                    nnode = g_clist[lo + npos];
                    ne0   = g_rowptr[nnode];
                    ndeg  = g_rowptr[nnode + 1] - ne0;
                    nxv   = g_x[nnode * 64 + f];
                    if (ndeg <= 64 && f < ndeg) esh[sub][buf ^ 1][f] = g_csrc[ne0 + f];
                }
                bar64(bid);
                float o = mm64t(hsh[sub], wt1, bias);
                g_h[node * 64 + f] = o;
                a1 += o; a2 += o * o;
                bar64(bid);

                node = nnode; e0 = ne0; deg = ndeg; xv = nxv; buf ^= 1;
            }
            atomicAdd(&s1sh[f], a1);
            atomicAdd(&s2sh[f], a2);
            __syncthreads();
            if (tid < 64) {
                atomicAdd(&g_stats[tc * 128 + tid],      s1sh[tid]);
                atomicAdd(&g_stats[tc * 128 + 64 + tid], s2sh[tid]);
            }
            grid_barrier();

            // === phase B: BN + ReLU + mm2, write back x ===
            const float* wt2 = Wsh2 + f * WSTRIDE;
            float bias2 = b2[tc * 64 + f];
            float cnt_f = (float)max(cnt, 1);
            float mean  = g_stats[tc * 128 + f] / cnt_f;
            float var   = g_stats[tc * 128 + 64 + f] / cnt_f - mean * mean;
            float inv   = rsqrtf(var + 1e-5f) * g1[tc * 64 + f];
            float beta  = be1[tc * 64 + f];

            int node2 = 0;
            float hv = 0.f;
            if (base < cnt) {
                node2 = g_clist[lo + base];
                hv    = g_h[node2 * 64 + f];
            }
            for (int pos = base; pos < cnt; pos += per) {
                hsh[sub][f] = fmaxf((hv - mean) * inv + beta, 0.f);
                int npos = pos + per;
                int nnode = 0;
                float nhv = 0.f;
                if (npos < cnt) {
                    nnode = g_clist[lo + npos];
                    nhv   = g_h[nnode * 64 + f];
                }
                bar64(bid);
                g_x[node2 * 64 + f] = mm64t(hsh[sub], wt2, bias2);
                bar64(bid);
                node2 = nnode; hv = nhv;
            }
            grid_barrier();
        }

        // ---- pooling for layer t: 256 blocks = 64 graphs x 4 chunks ----
        if (b < GG * 4) {
            const int g  = b >> 2;
            const int ch = b & 3;
            int* lohi = (int*)esh;
            if (tid < 2) {
                int target = g + tid;
                int lo2 = 0, hi2 = NN;
                while (lo2 < hi2) {
                    int m = (lo2 + hi2) >> 1;
                    if (load_idx(batch, m, is64) < target) lo2 = m + 1; else hi2 = m;
                }
                lohi[tid] = lo2;
            }
            __syncthreads();
            int lo2 = lohi[0], hi2 = lohi[1];
            int len = hi2 - lo2;
            int clo = lo2 + ((len * ch) >> 2);
            int chi = lo2 + ((len * (ch + 1)) >> 2);
            float s0 = 0.f, s1 = 0.f;
            int r = clo + sub;
            for (; r + 8 <= chi; r += 8) {
                s0 += g_x[r * 64 + f];
                s1 += g_x[(r + 4) * 64 + f];
            }
            for (; r < chi; r += 4) s0 += g_x[r * 64 + f];
            hsh[sub][f] = s0 + s1;
            __syncthreads();
            if (sub == 0) {
                float v = hsh[0][f] + hsh[1][f] + hsh[2][f] + hsh[3][f];
                atomicAdd(&g_z[g * (HH * LL) + t * 64 + f], v);
            }
        }
        grid_barrier();
    }

    // ---- F1: h1[g] = z[g] @ Wp1 + bp1 ----
    if (b < GG) {
        float* zsh = Wsh1;
        if (tid < HH * LL) zsh[tid] = g_z[b * (HH * LL) + tid];
        __syncthreads();
        float p = 0.f;
        int k0 = sub * 48;
#pragma unroll
        for (int k = 0; k < 48; ++k) p += zsh[k0 + k] * Wp1[(k0 + k) * 64 + f];
        hsh[sub][f] = p;
        __syncthreads();
        if (sub == 0)
            g_h1[b * 64 + f] = bp1[f] + ((hsh[0][f] + hsh[1][f]) + (hsh[2][f] + hsh[3][f]));
    }
    grid_barrier();

    // ---- F2: BN stats over graph rows (block 0) ----
    if (b == 0 && tid < 64) {
        float s = 0.f, q = 0.f;
        for (int g = 0; g < GG; ++g) { float v = g_h1[g * 64 + tid]; s += v; q += v * v; }
        float mean = s / (float)GG;
        float var  = q / (float)GG - mean * mean;
        g_bnp[tid]      = mean;
        g_bnp[64 + tid] = rsqrtf(var + 1e-5f) * gp[tid];
    }
    grid_barrier();

    // ---- F3: out[g] = relu(bn(h1[g])) @ Wp2 + bp2 ----
    if (b < GG) {
        float* vsh = Wsh1;
        if (tid < 64) {
            float v = g_h1[b * 64 + tid];
            vsh[tid] = fmaxf((v - g_bnp[tid]) * g_bnp[64 + tid] + bep[tid], 0.f);
        }
        __syncthreads();
        float p = 0.f;
        int k0 = sub * 16;
#pragma unroll
        for (int k = 0; k < 16; ++k) p += vsh[k0 + k] * Wp2[(k0 + k) * 64 + f];
        hsh[sub][f] = p;
        __syncthreads();
        if (sub == 0)
            out[b * 64 + f] = bp2[f] + ((hsh[0][f] + hsh[1][f]) + (hsh[2][f] + hsh[3][f]));
    }
}

// ---------------------------------------------------------------------------
extern "C" void kernel_launch(void* const* d_in, const int* in_sizes, int n_in,
                              void* d_out, int out_size) {
    const float* x     = (const float*)d_in[0];
    const int*   cl    = (const int*)d_in[1];
    const void*  eidx  = d_in[2];
    const void*  batch = d_in[3];
    const float* W1  = (const float*)d_in[4];
    const float* b1  = (const float*)d_in[5];
    const float* g1  = (const float*)d_in[6];
    const float* be1 = (const float*)d_in[7];
    const float* W2  = (const float*)d_in[8];
    const float* b2  = (const float*)d_in[9];
    const float* Wp1 = (const float*)d_in[10];
    const float* bp1 = (const float*)d_in[11];
    const float* gp  = (const float*)d_in[12];
    const float* bep = (const float*)d_in[13];
    const float* Wp2 = (const float*)d_in[14];
    const float* bp2 = (const float*)d_in[15];
    float* out = (float*)d_out;

    persistent_kernel<<<NB, NT>>>(x, cl, eidx, batch, W1, b1, g1, be1, W2, b2,
                                  Wp1, bp1, gp, bep, Wp2, bp2, out);
}

// round 16
// speedup vs baseline: 1.6592x; 1.1327x over previous
#include <cuda_runtime.h>

#define NN 50000
#define EE 800000
#define GG 64
#define HH 64
#define LL 3
#define CC 4
#define NH (NN*HH)
#define NB 296                 // 2 blocks/SM x 148 SMs, all co-resident
#define NT 256
#define NODE_CHUNK 169         // ceil(50000/296)

// ---------------------------------------------------------------------------
// Scratch
// ---------------------------------------------------------------------------
__device__ __align__(16) float g_x[NH];
__device__ __align__(16) float g_h[NH];
__device__ int   g_rowptr[NN+1];
__device__ int   g_cursor[NN];
__device__ int   g_deg[NN];
__device__ int   g_csrc[EE];
__device__ float g_stats[LL*CC*128];
__device__ float g_z[GG*HH*LL];
__device__ float g_h1[GG*HH];
__device__ float g_bnp[128];
__device__ int   g_ccnt[CC];
__device__ int   g_coff[CC+1];
__device__ int   g_ccur[CC];
__device__ int   g_clist[NN];
__device__ int   g_bsum[NB];
__device__ int   g_boff[NB];
__device__ int   g_is64;
__device__ unsigned int g_bar_arrive;
__device__ unsigned int g_bar_gen;

__device__ __forceinline__ int load_idx(const void* p, long long i, int is64) {
    if (is64) return (int)((const long long*)p)[i];
    return ((const int*)p)[i];
}

__device__ __forceinline__ void bar64(int id) {
    asm volatile("bar.sync %0, 64;" :: "r"(id) : "memory");
}

// Software grid barrier (all NB blocks co-resident by construction)
__device__ __forceinline__ void grid_barrier() {
    __syncthreads();
    if (threadIdx.x == 0) {
        __threadfence();
        volatile unsigned int* genp = &g_bar_gen;
        unsigned int gen = *genp;
        if (atomicAdd(&g_bar_arrive, 1u) == NB - 1) {
            g_bar_arrive = 0;
            __threadfence();
            *genp = gen + 1;
        } else {
            while (*genp == gen) { }
        }
    }
    __syncthreads();
}

// packed f32x2 fma: d = a*b + d  (elementwise on 2 fp32 lanes)
__device__ __forceinline__ void fma2(unsigned long long& d,
                                     unsigned long long a,
                                     unsigned long long b) {
    asm("fma.rn.f32x2 %0, %1, %2, %0;" : "+l"(d) : "l"(a), "l"(b));
}

// 64-wide inner product with packed FMA. h read as ulonglong2 (LDS.128 -> two
// packed f32x2 operands, no pack instructions). wc = 32 pre-packed W pairs:
// wc[k] = {W[2k][f], W[2k+1][f]}.
__device__ __forceinline__ float mm64p(const float* hp,
                                       const unsigned long long* wc,
                                       float bias) {
    const ulonglong2* hp2 = (const ulonglong2*)hp;
    unsigned long long a0 = 0ull, a1 = 0ull;
#pragma unroll
    for (int j = 0; j < 16; ++j) {
        ulonglong2 hv = hp2[j];
        fma2(a0, hv.x, wc[2*j]);
        fma2(a1, hv.y, wc[2*j+1]);
    }
    float e0, o0, e1, o1;
    asm("mov.b64 {%0,%1}, %2;" : "=f"(e0), "=f"(o0) : "l"(a0));
    asm("mov.b64 {%0,%1}, %2;" : "=f"(e1), "=f"(o1) : "l"(a1));
    return bias + ((e0 + o0) + (e1 + o1));
}

// pack W column for feature f from row-major Wsh into 32 f32x2 pairs
__device__ __forceinline__ void pack_wcol(const float* Wsh, int f,
                                          unsigned long long* wc) {
#pragma unroll
    for (int k = 0; k < 32; ++k) {
        float lo = Wsh[(2*k) * 64 + f];
        float hi = Wsh[(2*k+1) * 64 + f];
        asm("mov.b64 %0, {%1,%2};" : "=l"(wc[k]) : "f"(lo), "f"(hi));
    }
}

// ---------------------------------------------------------------------------
// Single persistent kernel: everything
// ---------------------------------------------------------------------------
__global__ void __launch_bounds__(NT, 2) persistent_kernel(
        const float* __restrict__ x, const int* __restrict__ cl,
        const void* __restrict__ eidx, const void* __restrict__ batch,
        const float* __restrict__ W1, const float* __restrict__ b1,
        const float* __restrict__ g1, const float* __restrict__ be1,
        const float* __restrict__ W2, const float* __restrict__ b2,
        const float* __restrict__ Wp1, const float* __restrict__ bp1,
        const float* __restrict__ gp,  const float* __restrict__ bep,
        const float* __restrict__ Wp2, const float* __restrict__ bp2,
        float* __restrict__ out) {
    __shared__ __align__(16) float Wsh1[4096];
    __shared__ __align__(16) float Wsh2[4096];
    __shared__ __align__(16) float hshp[2][4][64];   // parity-alternating h buffers
    __shared__ __align__(16) int   esh[4][2][64];    // reused as int sh[512] in scans
    __shared__ float s1sh[64], s2sh[64];

    const int tid = threadIdx.x;
    const int b   = blockIdx.x;
    const int gtid = b * NT + tid;
    const int gstride = NB * NT;
    const int sub = tid >> 6;
    const int f   = tid & 63;
    const int bid = sub + 1;

    // ---- P0: init + dtype detect ----
    for (int i = gtid; i < NH / 4; i += gstride)
        ((float4*)g_x)[i] = ((const float4*)x)[i];
    for (int i = gtid; i < NN; i += gstride) g_deg[i] = 0;
    for (int i = gtid; i < LL*CC*128; i += gstride) g_stats[i] = 0.f;
    for (int i = gtid; i < GG*HH*LL; i += gstride) g_z[i] = 0.f;
    if (gtid < CC) g_ccnt[gtid] = 0;
    if (b == 0) {
        const int* e32 = (const int*)eidx;
        int bad = 0;
        for (int k = tid; k < 1024; k += NT) if (e32[2 * k + 1] != 0) bad = 1;
        int* sh = (int*)esh;
        sh[tid] = bad;
        __syncthreads();
        for (int s = 128; s > 0; s >>= 1) {
            if (tid < s) sh[tid] |= sh[tid + s];
            __syncthreads();
        }
        if (tid == 0) g_is64 = !sh[0];
    }
    grid_barrier();
    const int is64 = g_is64;

    // ---- P1: degree + cluster count ----
    for (int i = gtid; i < EE; i += gstride) {
        int d = load_idx(eidx, (long long)EE + i, is64);
        atomicAdd(&g_deg[d], 1);
    }
    for (int i = gtid; i < NN; i += gstride) atomicAdd(&g_ccnt[cl[i]], 1);
    grid_barrier();

    // ---- P2: cluster offsets (block0) + local inclusive degree scans ----
    if (b == 0 && tid == 0) {
        int acc = 0;
        for (int c = 0; c < CC; ++c) { g_coff[c] = acc; g_ccur[c] = acc; acc += g_ccnt[c]; }
        g_coff[CC] = acc;
    }
    {
        int* sh = (int*)esh;
        int idx = b * NODE_CHUNK + tid;
        int v = (tid < NODE_CHUNK && idx < NN) ? g_deg[idx] : 0;
        sh[tid] = v;
        __syncthreads();
        for (int s = 1; s < NT; s <<= 1) {
            int tv = (tid >= s) ? sh[tid - s] : 0;
            __syncthreads();
            sh[tid] += tv;
            __syncthreads();
        }
        if (tid < NODE_CHUNK && idx < NN) g_rowptr[idx] = sh[tid];
        if (tid == NT - 1) g_bsum[b] = sh[NT - 1];
    }
    grid_barrier();

    // ---- P3: scan block sums (block0); fill cluster lists (all) ----
    if (b == 0 && tid == 0) {
        int acc = 0;
        for (int i = 0; i < NB; ++i) { int t = g_bsum[i]; g_boff[i] = acc; acc += t; }
        g_rowptr[NN] = acc;
    }
    for (int i = gtid; i < NN; i += gstride) {
        int pos = atomicAdd(&g_ccur[cl[i]], 1);
        g_clist[pos] = i;
    }
    grid_barrier();

    // ---- P4: finalize rowptr/cursor ----
    {
        int idx = b * NODE_CHUNK + tid;
        if (tid < NODE_CHUNK && idx < NN) {
            int excl = g_boff[b] + g_rowptr[idx] - g_deg[idx];
            g_rowptr[idx] = excl;
            g_cursor[idx] = excl;
        }
    }
    grid_barrier();

    // ---- P5: CSR fill ----
    for (int i = gtid; i < EE; i += gstride) {
        int s = load_idx(eidx, i, is64);
        int d = load_idx(eidx, (long long)EE + i, is64);
        int pos = atomicAdd(&g_cursor[d], 1);
        g_csrc[pos] = s;
    }
    grid_barrier();

    // ---- main loop: 3 layers x 4 clusters ----
    unsigned long long wc[32];
    for (int t = 0; t < LL; ++t) {
        for (int c = 0; c < CC; ++c) {
            const int tc = t * CC + c;
            for (int i = tid; i < 4096; i += NT) {
                Wsh1[i] = W1[tc * 4096 + i];
                Wsh2[i] = W2[tc * 4096 + i];
            }
            if (tid < 64) { s1sh[tid] = 0.f; s2sh[tid] = 0.f; }
            __syncthreads();

            // === phase A: gather + mm1 + stats (1 bar/node) ===
            pack_wcol(Wsh1, f, wc);
            float bias = b1[tc * 64 + f];

            const int lo  = g_coff[c];
            const int cnt = g_coff[c + 1] - lo;
            const int per = NB * 4;
            const int base = b * 4 + sub;

            float a1 = 0.f, a2 = 0.f;
            int buf = 0, itp = 0;
            int node = 0, e0 = 0, deg = 0;
            float xv = 0.f;
            if (base < cnt) {
                node = g_clist[lo + base];
                e0   = g_rowptr[node];
                deg  = g_rowptr[node + 1] - e0;
                xv   = g_x[node * 64 + f];
                if (deg <= 64 && f < deg) esh[sub][0][f] = g_csrc[e0 + f];
            }
            bar64(bid);

            for (int pos = base; pos < cnt; pos += per) {
                float acc0 = xv, acc1 = 0.f, acc2 = 0.f, acc3 = 0.f;
                float acc4 = 0.f, acc5 = 0.f, acc6 = 0.f, acc7 = 0.f;
                if (deg <= 64) {
                    const int* ep = esh[sub][buf];
                    int i = 0;
                    for (; i + 8 <= deg; i += 8) {
                        int s0 = ep[i+0], s1 = ep[i+1], s2 = ep[i+2], s3 = ep[i+3];
                        int s4 = ep[i+4], s5 = ep[i+5], s6 = ep[i+6], s7 = ep[i+7];
                        acc0 += g_x[s0 * 64 + f];
                        acc1 += g_x[s1 * 64 + f];
                        acc2 += g_x[s2 * 64 + f];
                        acc3 += g_x[s3 * 64 + f];
                        acc4 += g_x[s4 * 64 + f];
                        acc5 += g_x[s5 * 64 + f];
                        acc6 += g_x[s6 * 64 + f];
                        acc7 += g_x[s7 * 64 + f];
                    }
                    for (; i < deg; ++i) acc0 += g_x[ep[i] * 64 + f];
                } else {
                    // rare (deg>64): direct-global gather (broadcast csrc reads)
                    int e = e0;
                    const int e1 = e0 + deg;
                    for (; e + 8 <= e1; e += 8) {
                        int s0 = g_csrc[e+0], s1 = g_csrc[e+1], s2 = g_csrc[e+2], s3 = g_csrc[e+3];
                        int s4 = g_csrc[e+4], s5 = g_csrc[e+5], s6 = g_csrc[e+6], s7 = g_csrc[e+7];
                        acc0 += g_x[s0 * 64 + f];
                        acc1 += g_x[s1 * 64 + f];
                        acc2 += g_x[s2 * 64 + f];
                        acc3 += g_x[s3 * 64 + f];
                        acc4 += g_x[s4 * 64 + f];
                        acc5 += g_x[s5 * 64 + f];
                        acc6 += g_x[s6 * 64 + f];
                        acc7 += g_x[s7 * 64 + f];
                    }
                    for (; e < e1; ++e) acc0 += g_x[g_csrc[e] * 64 + f];
                }
                hshp[itp][sub][f] = ((acc0 + acc1) + (acc2 + acc3)) + ((acc4 + acc5) + (acc6 + acc7));

                // prestage next node (writes esh[buf^1]; ordered vs other warp's
                // reads of esh[buf] by the PREVIOUS iteration's bar)
                int npos = pos + per;
                int nnode = 0, ne0 = 0, ndeg = 0;
                float nxv = 0.f;
                if (npos < cnt) {
                    nnode = g_clist[lo + npos];
                    ne0   = g_rowptr[nnode];
                    ndeg  = g_rowptr[nnode + 1] - ne0;
                    nxv   = g_x[nnode * 64 + f];
                    if (ndeg <= 64 && f < ndeg) esh[sub][buf ^ 1][f] = g_csrc[ne0 + f];
                }
                bar64(bid);
                float o = mm64p(hshp[itp][sub], wc, bias);
                g_h[node * 64 + f] = o;
                a1 += o; a2 += o * o;
                // no second bar: next iteration writes hshp[itp^1] (distinct)

                node = nnode; e0 = ne0; deg = ndeg; xv = nxv; buf ^= 1; itp ^= 1;
            }
            atomicAdd(&s1sh[f], a1);
            atomicAdd(&s2sh[f], a2);
            __syncthreads();
            if (tid < 64) {
                atomicAdd(&g_stats[tc * 128 + tid],      s1sh[tid]);
                atomicAdd(&g_stats[tc * 128 + 64 + tid], s2sh[tid]);
            }
            grid_barrier();

            // === phase B: BN + ReLU + mm2, write back x (1 bar/node) ===
            pack_wcol(Wsh2, f, wc);
            float bias2 = b2[tc * 64 + f];
            float cnt_f = (float)max(cnt, 1);
            float mean  = g_stats[tc * 128 + f] / cnt_f;
            float var   = g_stats[tc * 128 + 64 + f] / cnt_f - mean * mean;
            float inv   = rsqrtf(var + 1e-5f) * g1[tc * 64 + f];
            float beta  = be1[tc * 64 + f];

            itp = 0;
            int node2 = 0;
            float hv = 0.f;
            if (base < cnt) {
                node2 = g_clist[lo + base];
                hv    = g_h[node2 * 64 + f];
            }
            for (int pos = base; pos < cnt; pos += per) {
                hshp[itp][sub][f] = fmaxf((hv - mean) * inv + beta, 0.f);
                int npos = pos + per;
                int nnode = 0;
                float nhv = 0.f;
                if (npos < cnt) {
                    nnode = g_clist[lo + npos];
                    nhv   = g_h[nnode * 64 + f];
                }
                bar64(bid);
                g_x[node2 * 64 + f] = mm64p(hshp[itp][sub], wc, bias2);
                // no second bar: next iteration writes hshp[itp^1]
                node2 = nnode; hv = nhv; itp ^= 1;
            }
            grid_barrier();
        }

        // ---- pooling for layer t: 256 blocks = 64 graphs x 4 chunks ----
        if (b < GG * 4) {
            const int g  = b >> 2;
            const int ch = b & 3;
            int* lohi = (int*)esh;
            if (tid < 2) {
                int target = g + tid;
                int lo2 = 0, hi2 = NN;
                while (lo2 < hi2) {
                    int m = (lo2 + hi2) >> 1;
                    if (load_idx(batch, m, is64) < target) lo2 = m + 1; else hi2 = m;
                }
                lohi[tid] = lo2;
            }
            __syncthreads();
            int lo2 = lohi[0], hi2 = lohi[1];
            int len = hi2 - lo2;
            int clo = lo2 + ((len * ch) >> 2);
            int chi = lo2 + ((len * (ch + 1)) >> 2);
            float s0 = 0.f, s1 = 0.f;
            int r = clo + sub;
            for (; r + 8 <= chi; r += 8) {
                s0 += g_x[r * 64 + f];
                s1 += g_x[(r + 4) * 64 + f];
            }
            for (; r < chi; r += 4) s0 += g_x[r * 64 + f];
            hshp[0][sub][f] = s0 + s1;
            __syncthreads();
            if (sub == 0) {
                float v = hshp[0][0][f] + hshp[0][1][f] + hshp[0][2][f] + hshp[0][3][f];
                atomicAdd(&g_z[g * (HH * LL) + t * 64 + f], v);
            }
        }
        grid_barrier();
    }

    // ---- F1: h1[g] = z[g] @ Wp1 + bp1 ----
    if (b < GG) {
        float* zsh = Wsh1;
        if (tid < HH * LL) zsh[tid] = g_z[b * (HH * LL) + tid];
        __syncthreads();
        float p = 0.f;
        int k0 = sub * 48;
#pragma unroll
        for (int k = 0; k < 48; ++k) p += zsh[k0 + k] * Wp1[(k0 + k) * 64 + f];
        hshp[0][sub][f] = p;
        __syncthreads();
        if (sub == 0)
            g_h1[b * 64 + f] = bp1[f] + ((hshp[0][0][f] + hshp[0][1][f]) + (hshp[0][2][f] + hshp[0][3][f]));
    }
    grid_barrier();

    // ---- F2: BN stats over graph rows (block 0) ----
    if (b == 0 && tid < 64) {
        float s = 0.f, q = 0.f;
        for (int g = 0; g < GG; ++g) { float v = g_h1[g * 64 + tid]; s += v; q += v * v; }
        float mean = s / (float)GG;
        float var  = q / (float)GG - mean * mean;
        g_bnp[tid]      = mean;
        g_bnp[64 + tid] = rsqrtf(var + 1e-5f) * gp[tid];
    }
    grid_barrier();

    // ---- F3: out[g] = relu(bn(h1[g])) @ Wp2 + bp2 ----
    if (b < GG) {
        float* vsh = Wsh1;
        if (tid < 64) {
            float v = g_h1[b * 64 + tid];
            vsh[tid] = fmaxf((v - g_bnp[tid]) * g_bnp[64 + tid] + bep[tid], 0.f);
        }
        __syncthreads();
        float p = 0.f;
        int k0 = sub * 16;
#pragma unroll
        for (int k = 0; k < 16; ++k) p += vsh[k0 + k] * Wp2[(k0 + k) * 64 + f];
        hshp[0][sub][f] = p;
        __syncthreads();
        if (sub == 0)
            out[b * 64 + f] = bp2[f] + ((hshp[0][0][f] + hshp[0][1][f]) + (hshp[0][2][f] + hshp[0][3][f]));
    }
}

// ---------------------------------------------------------------------------
extern "C" void kernel_launch(void* const* d_in, const int* in_sizes, int n_in,
                              void* d_out, int out_size) {
    const float* x     = (const float*)d_in[0];
    const int*   cl    = (const int*)d_in[1];
    const void*  eidx  = d_in[2];
    const void*  batch = d_in[3];
    const float* W1  = (const float*)d_in[4];
    const float* b1  = (const float*)d_in[5];
    const float* g1  = (const float*)d_in[6];
    const float* be1 = (const float*)d_in[7];
    const float* W2  = (const float*)d_in[8];
    const float* b2  = (const float*)d_in[9];
    const float* Wp1 = (const float*)d_in[10];
    const float* bp1 = (const float*)d_in[11];
    const float* gp  = (const float*)d_in[12];
    const float* bep = (const float*)d_in[13];
    const float* Wp2 = (const float*)d_in[14];
    const float* bp2 = (const float*)d_in[15];
    float* out = (float*)d_out;

    persistent_kernel<<<NB, NT>>>(x, cl, eidx, batch, W1, b1, g1, be1, W2, b2,
                                  Wp1, bp1, gp, bep, Wp2, bp2, out);
}